// round 2
// baseline (speedup 1.0000x reference)
#include <cuda_runtime.h>
#include <cstdint>
#include <cmath>

#define N_LEVELS 16
#define HASHMAP_SIZE 32768u
#define HASH_MASK 32767u
#define P1 2654435761u
#define P2 805459861u

// 4 MB materialized per-level tables (LoRA A@B), device-global scratch (no alloc).
__device__ float2 g_tables[N_LEVELS * HASHMAP_SIZE];

struct ResArr { float r[N_LEVELS]; };

// ---------------- Kernel 1: materialize tables = einsum('lsr,lrf->lsf') ----------------
__global__ void materialize_kernel(const float* __restrict__ tableA,
                                   const float* __restrict__ tableB) {
    int t = blockIdx.x * blockDim.x + threadIdx.x;           // [0, 16*32768)
    if (t >= N_LEVELS * (int)HASHMAP_SIZE) return;
    int l = t >> 15;
    float4 a = __ldg(((const float4*)tableA) + t);           // A[l, s, 0:4]
    const float* Bl = tableB + l * 8;                        // B[l, r, f], r-major
    float b00 = __ldg(Bl + 0), b01 = __ldg(Bl + 1);
    float b10 = __ldg(Bl + 2), b11 = __ldg(Bl + 3);
    float b20 = __ldg(Bl + 4), b21 = __ldg(Bl + 5);
    float b30 = __ldg(Bl + 6), b31 = __ldg(Bl + 7);
    float f0 = a.x * b00 + a.y * b10 + a.z * b20 + a.w * b30;
    float f1 = a.x * b01 + a.y * b11 + a.z * b21 + a.w * b31;
    g_tables[t] = make_float2(f0, f1);
}

// ---------------- Kernel 2: hash-grid trilinear encode ----------------
__global__ void __launch_bounds__(256)
encode_kernel(const float* __restrict__ x, float* __restrict__ out, int n, ResArr res) {
    int i = blockIdx.x * blockDim.x + threadIdx.x;
    if (i >= n) return;

    // normalize to [0,1]: (x + 1) / 2  (exact as *0.5f)
    float x0 = (x[3 * i + 0] + 1.0f) * 0.5f;
    float x1 = (x[3 * i + 1] + 1.0f) * 0.5f;
    float x2 = (x[3 * i + 2] + 1.0f) * 0.5f;

    float acc[2 * N_LEVELS];

#pragma unroll
    for (int l = 0; l < N_LEVELS; l++) {
        float r = res.r[l];
        float xl0 = x0 * r, xl1 = x1 * r, xl2 = x2 * r;
        float f0 = floorf(xl0), f1 = floorf(xl1), f2 = floorf(xl2);
        float w0 = xl0 - f0, w1 = xl1 - f1, w2 = xl2 - f2;
        float v0 = 1.0f - w0, v1 = 1.0f - w1, v2 = 1.0f - w2;
        uint32_t i0 = (uint32_t)f0;
        uint32_t i1 = (uint32_t)f1;
        uint32_t i2 = (uint32_t)f2;

        uint32_t h1a = i1 * P1;          uint32_t h1b = h1a + P1;
        uint32_t h2a = i2 * P2;          uint32_t h2b = h2a + P2;
        uint32_t i0b = i0 + 1u;

        const float2* __restrict__ tl = g_tables + (l << 15);

        // 8 corner gathers first (max MLP), then weight FMAs.
        uint32_t idx0 = (i0  ^ h1a ^ h2a) & HASH_MASK;
        uint32_t idx1 = (i0b ^ h1a ^ h2a) & HASH_MASK;
        uint32_t idx2 = (i0  ^ h1b ^ h2a) & HASH_MASK;
        uint32_t idx3 = (i0b ^ h1b ^ h2a) & HASH_MASK;
        uint32_t idx4 = (i0  ^ h1a ^ h2b) & HASH_MASK;
        uint32_t idx5 = (i0b ^ h1a ^ h2b) & HASH_MASK;
        uint32_t idx6 = (i0  ^ h1b ^ h2b) & HASH_MASK;
        uint32_t idx7 = (i0b ^ h1b ^ h2b) & HASH_MASK;

        float2 t0 = __ldg(tl + idx0);
        float2 t1 = __ldg(tl + idx1);
        float2 t2 = __ldg(tl + idx2);
        float2 t3 = __ldg(tl + idx3);
        float2 t4 = __ldg(tl + idx4);
        float2 t5 = __ldg(tl + idx5);
        float2 t6 = __ldg(tl + idx6);
        float2 t7 = __ldg(tl + idx7);

        float wc0 = v0 * v1 * v2;
        float wc1 = w0 * v1 * v2;
        float wc2 = v0 * w1 * v2;
        float wc3 = w0 * w1 * v2;
        float wc4 = v0 * v1 * w2;
        float wc5 = w0 * v1 * w2;
        float wc6 = v0 * w1 * w2;
        float wc7 = w0 * w1 * w2;

        float a0 = t0.x * wc0, a1 = t0.y * wc0;
        a0 = fmaf(t1.x, wc1, a0); a1 = fmaf(t1.y, wc1, a1);
        a0 = fmaf(t2.x, wc2, a0); a1 = fmaf(t2.y, wc2, a1);
        a0 = fmaf(t3.x, wc3, a0); a1 = fmaf(t3.y, wc3, a1);
        a0 = fmaf(t4.x, wc4, a0); a1 = fmaf(t4.y, wc4, a1);
        a0 = fmaf(t5.x, wc5, a0); a1 = fmaf(t5.y, wc5, a1);
        a0 = fmaf(t6.x, wc6, a0); a1 = fmaf(t6.y, wc6, a1);
        a0 = fmaf(t7.x, wc7, a0); a1 = fmaf(t7.y, wc7, a1);

        acc[2 * l + 0] = a0;
        acc[2 * l + 1] = a1;
    }

    // Each thread writes its own contiguous 128B (32 floats), 128B-aligned.
    float4* o = (float4*)(out + (size_t)i * (2 * N_LEVELS));
#pragma unroll
    for (int k = 0; k < 8; k++) {
        o[k] = make_float4(acc[4 * k + 0], acc[4 * k + 1],
                           acc[4 * k + 2], acc[4 * k + 3]);
    }
}

extern "C" void kernel_launch(void* const* d_in, const int* in_sizes, int n_in,
                              void* d_out, int out_size) {
    const float* x       = (const float*)d_in[0];   // [N, 3]
    const float* tableA  = (const float*)d_in[1];   // [16, 32768, 4]
    const float* tableB  = (const float*)d_in[2];   // [16, 4, 2]
    float* out           = (float*)d_out;           // [N, 32]
    int n = in_sizes[0] / 3;

    // Resolutions: replicate numpy's float64 computation exactly to avoid
    // floor-boundary mismatches at the power-of-two levels.
    ResArr res;
    {
        double b = exp((log(512.0) - log(16.0)) / (double)(N_LEVELS - 1));
        for (int l = 0; l < N_LEVELS; l++)
            res.r[l] = (float)floor(16.0 * pow(b, (double)l));
    }

    int tab_entries = N_LEVELS * (int)HASHMAP_SIZE;
    materialize_kernel<<<(tab_entries + 255) / 256, 256>>>(tableA, tableB);
    encode_kernel<<<(n + 255) / 256, 256>>>(x, out, n, res);
}

// round 4
// speedup vs baseline: 1.1775x; 1.1775x over previous
#include <cuda_runtime.h>
#include <cstdint>
#include <cmath>

#define N_LEVELS 16
#define HASHMAP_SIZE 32768u
#define HASH_MASK 32767u
#define P1 2654435761u
#define P2 805459861u

// 4 MB materialized per-level tables (LoRA A@B), device-global scratch (no alloc).
__device__ float2 g_tables[N_LEVELS * HASHMAP_SIZE];

struct ResArr { float r[N_LEVELS]; };

// ---------------- Kernel 1: materialize tables = einsum('lsr,lrf->lsf') ----------------
__global__ void materialize_kernel(const float* __restrict__ tableA,
                                   const float* __restrict__ tableB) {
    int t = blockIdx.x * blockDim.x + threadIdx.x;           // [0, 16*32768)
    if (t >= N_LEVELS * (int)HASHMAP_SIZE) return;
    int l = t >> 15;
    float4 a = __ldg(((const float4*)tableA) + t);           // A[l, s, 0:4]
    const float* Bl = tableB + l * 8;                        // B[l, r, f], r-major
    float b00 = __ldg(Bl + 0), b01 = __ldg(Bl + 1);
    float b10 = __ldg(Bl + 2), b11 = __ldg(Bl + 3);
    float b20 = __ldg(Bl + 4), b21 = __ldg(Bl + 5);
    float b30 = __ldg(Bl + 6), b31 = __ldg(Bl + 7);
    float f0 = a.x * b00 + a.y * b10 + a.z * b20 + a.w * b30;
    float f1 = a.x * b01 + a.y * b11 + a.z * b21 + a.w * b31;
    g_tables[t] = make_float2(f0, f1);
}

// ---------------- Kernel 2: hash-grid trilinear encode ----------------
// 8 threads per point; thread p of a point handles levels 2p and 2p+1 and
// writes one float4 of the output row (perfectly coalesced across threads).
__global__ void __launch_bounds__(256)
encode_kernel(const float* __restrict__ x, float* __restrict__ out, int n, ResArr res) {
    int t = blockIdx.x * blockDim.x + threadIdx.x;
    int i = t >> 3;            // point index
    int p = t & 7;             // level-pair index (levels 2p, 2p+1)
    if (i >= n) return;

    // normalize to [0,1]: (x + 1) / 2  (exact as *0.5f); warp-broadcast loads
    float x0 = (__ldg(x + 3 * i + 0) + 1.0f) * 0.5f;
    float x1 = (__ldg(x + 3 * i + 1) + 1.0f) * 0.5f;
    float x2 = (__ldg(x + 3 * i + 2) + 1.0f) * 0.5f;

    float acc[4];

#pragma unroll
    for (int u = 0; u < 2; u++) {
        int l = 2 * p + u;
        float r = res.r[l];
        float xl0 = x0 * r, xl1 = x1 * r, xl2 = x2 * r;
        float f0 = floorf(xl0), f1 = floorf(xl1), f2 = floorf(xl2);
        float w0 = xl0 - f0, w1 = xl1 - f1, w2 = xl2 - f2;
        float v0 = 1.0f - w0, v1 = 1.0f - w1, v2 = 1.0f - w2;
        uint32_t i0 = (uint32_t)f0;
        uint32_t i1 = (uint32_t)f1;
        uint32_t i2 = (uint32_t)f2;

        uint32_t h1a = i1 * P1;          uint32_t h1b = h1a + P1;
        uint32_t h2a = i2 * P2;          uint32_t h2b = h2a + P2;
        uint32_t i0b = i0 + 1u;
        bool odd = (i0 & 1u) != 0u;      // shared by all 4 x-pairs of this level

        const float2* __restrict__ tl  = g_tables + (l << 15);
        const float4* __restrict__ tl4 = (const float4*)tl;

        uint32_t idx0 = (i0  ^ h1a ^ h2a) & HASH_MASK;
        uint32_t idx1 = (i0b ^ h1a ^ h2a) & HASH_MASK;
        uint32_t idx2 = (i0  ^ h1b ^ h2a) & HASH_MASK;
        uint32_t idx3 = (i0b ^ h1b ^ h2a) & HASH_MASK;
        uint32_t idx4 = (i0  ^ h1a ^ h2b) & HASH_MASK;
        uint32_t idx5 = (i0b ^ h1a ^ h2b) & HASH_MASK;
        uint32_t idx6 = (i0  ^ h1b ^ h2b) & HASH_MASK;
        uint32_t idx7 = (i0b ^ h1b ^ h2b) & HASH_MASK;

        // Paired gathers: each float4 covers {idx, idx^1}. When i0 is even,
        // the x+1 corner IS idx^1, so one 16B load serves both corners.
        float4 q0 = __ldg(tl4 + (idx0 >> 1));
        float4 q2 = __ldg(tl4 + (idx2 >> 1));
        float4 q4 = __ldg(tl4 + (idx4 >> 1));
        float4 q6 = __ldg(tl4 + (idx6 >> 1));

        // Odd-i0 fallback loads for the x+1 corners (predicated).
        float2 s1 = make_float2(0.f, 0.f), s3 = s1, s5 = s1, s7 = s1;
        if (odd) {
            s1 = __ldg(tl + idx1);
            s3 = __ldg(tl + idx3);
            s5 = __ldg(tl + idx5);
            s7 = __ldg(tl + idx7);
        }

        bool hi0 = (idx0 & 1u) != 0u;    // same low bit for idx0/2/4/6 (parity of h terms shared? no — per-index)
        bool hi2 = (idx2 & 1u) != 0u;
        bool hi4 = (idx4 & 1u) != 0u;
        bool hi6 = (idx6 & 1u) != 0u;

        float2 t0 = hi0 ? make_float2(q0.z, q0.w) : make_float2(q0.x, q0.y);
        float2 t2 = hi2 ? make_float2(q2.z, q2.w) : make_float2(q2.x, q2.y);
        float2 t4 = hi4 ? make_float2(q4.z, q4.w) : make_float2(q4.x, q4.y);
        float2 t6 = hi6 ? make_float2(q6.z, q6.w) : make_float2(q6.x, q6.y);

        float2 t1 = odd ? s1 : (hi0 ? make_float2(q0.x, q0.y) : make_float2(q0.z, q0.w));
        float2 t3 = odd ? s3 : (hi2 ? make_float2(q2.x, q2.y) : make_float2(q2.z, q2.w));
        float2 t5 = odd ? s5 : (hi4 ? make_float2(q4.x, q4.y) : make_float2(q4.z, q4.w));
        float2 t7 = odd ? s7 : (hi6 ? make_float2(q6.x, q6.y) : make_float2(q6.z, q6.w));

        float wc0 = v0 * v1 * v2;
        float wc1 = w0 * v1 * v2;
        float wc2 = v0 * w1 * v2;
        float wc3 = w0 * w1 * v2;
        float wc4 = v0 * v1 * w2;
        float wc5 = w0 * v1 * w2;
        float wc6 = v0 * w1 * w2;
        float wc7 = w0 * w1 * w2;

        float a0 = t0.x * wc0, a1 = t0.y * wc0;
        a0 = fmaf(t1.x, wc1, a0); a1 = fmaf(t1.y, wc1, a1);
        a0 = fmaf(t2.x, wc2, a0); a1 = fmaf(t2.y, wc2, a1);
        a0 = fmaf(t3.x, wc3, a0); a1 = fmaf(t3.y, wc3, a1);
        a0 = fmaf(t4.x, wc4, a0); a1 = fmaf(t4.y, wc4, a1);
        a0 = fmaf(t5.x, wc5, a0); a1 = fmaf(t5.y, wc5, a1);
        a0 = fmaf(t6.x, wc6, a0); a1 = fmaf(t6.y, wc6, a1);
        a0 = fmaf(t7.x, wc7, a0); a1 = fmaf(t7.y, wc7, a1);

        acc[2 * u + 0] = a0;
        acc[2 * u + 1] = a1;
    }

    // thread writes its float4 slice of the point's 32-float output row
    float4* o = (float4*)(out + (size_t)i * (2 * N_LEVELS)) + p;
    *o = make_float4(acc[0], acc[1], acc[2], acc[3]);
}

extern "C" void kernel_launch(void* const* d_in, const int* in_sizes, int n_in,
                              void* d_out, int out_size) {
    const float* x       = (const float*)d_in[0];   // [N, 3]
    const float* tableA  = (const float*)d_in[1];   // [16, 32768, 4]
    const float* tableB  = (const float*)d_in[2];   // [16, 4, 2]
    float* out           = (float*)d_out;           // [N, 32]
    int n = in_sizes[0] / 3;

    // Resolutions: replicate numpy's float64 computation exactly to avoid
    // floor-boundary mismatches at the power-of-two levels.
    ResArr res;
    {
        double b = exp((log(512.0) - log(16.0)) / (double)(N_LEVELS - 1));
        for (int l = 0; l < N_LEVELS; l++)
            res.r[l] = (float)floor(16.0 * pow(b, (double)l));
    }

    int tab_entries = N_LEVELS * (int)HASHMAP_SIZE;
    materialize_kernel<<<(tab_entries + 255) / 256, 256>>>(tableA, tableB);

    int total = n * 8;
    encode_kernel<<<(total + 255) / 256, 256>>>(x, out, n, res);
}